// round 13
// baseline (speedup 1.0000x reference)
#include <cuda_runtime.h>
#include <cuda_fp16.h>
#include <cstdint>

// ---------------- problem constants ----------------
#define EMBD   256
#define HIDDEN 256
#define HNUM   8
#define CHD    32
#define BATCH  8
#define NQ     1024
#define ITOT   21760
#define QPW    384
#define GK     256
#define BNH    (BATCH * NQ * HNUM)   // 65536

// ---------------- scratch ----------------
__device__ __half  g_img_p[BATCH * ITOT * HIDDEN];
__device__ __half  g_Wt1[HIDDEN * GK];
__device__ __half  g_Wt2[QPW * GK];
__device__ __half  g_Wt3[EMBD * GK];
__device__ float   g_qp[BATCH * NQ * QPW];
__device__ float   g_hidden[BATCH * NQ * HIDDEN];

__constant__ int c_sh[4]    = {128, 64, 32, 16};
__constant__ int c_start[4] = {0, 16384, 20480, 21504};

// ---------------- helpers ----------------
__device__ __forceinline__ void cp16(uint32_t dst, const void* src) {
    asm volatile("cp.async.cg.shared.global [%0], [%1], 16;" :: "r"(dst), "l"(src));
}
__device__ __forceinline__ uint32_t smem_u32(const void* p) {
    uint32_t a;
    asm("{ .reg .u64 t; cvta.to.shared.u64 t, %1; cvt.u32.u64 %0, t; }" : "=r"(a) : "l"(p));
    return a;
}
__device__ __forceinline__ uint32_t pack_h2(float lo, float hi) {
    uint32_t r;
    asm("cvt.rn.f16x2.f32 %0, %1, %2;" : "=r"(r) : "f"(hi), "f"(lo));
    return r;
}

// ================= GEMM1 tile (fp16 MMA, f32 acc, ldmatrix), C fp16 =================
#define APITCH  24
#define STG_H   (128 * APITCH)
#define NST     3
#define NKT16   (GK / 16)

__device__ void gemm1_tile(const float* __restrict__ Arows, const __half* __restrict__ Wt,
                           const float* __restrict__ bias, __half* __restrict__ Crows,
                           int n0, char* dynsm)
{
    __half* sA16 = (__half*)dynsm;
    __half* sB16 = sA16 + NST * STG_H;

    const int tid = threadIdx.x;
    const int wid = tid >> 5;
    const int lane = tid & 31;
    const int g = lane >> 2;
    const int tig = lane & 3;
    const int wm = (wid & 1) * 64;
    const int wn = (wid >> 1) * 32;

    const uint32_t lds_a_off = (uint32_t)((wm + (lane & 15)) * APITCH + (lane >> 4) * 8) * 2;

    uint32_t sbA[NST], sbB[NST];
    #pragma unroll
    for (int s = 0; s < NST; s++) {
        sbA[s] = smem_u32(sA16 + s * STG_H);
        sbB[s] = smem_u32(sB16 + s * STG_H);
    }

    const int arow = tid >> 1, aseg = tid & 1;
    const float* Ab = Arows + (size_t)arow * GK + aseg * 8;
    const __half* Bb = Wt + (size_t)(n0 + arow) * GK + aseg * 8;
    const uint32_t st_off = (uint32_t)(arow * APITCH + aseg * 8) * 2;

    float4 rA[2][2];
    auto ldgA = [&](int kt, int slot) {
        const float* p = Ab + kt * 16;
        rA[slot][0] = *(const float4*)p;
        rA[slot][1] = *(const float4*)(p + 4);
    };
    auto stsA = [&](int buf, int slot) {
        uint4 v;
        v.x = pack_h2(rA[slot][0].x, rA[slot][0].y);
        v.y = pack_h2(rA[slot][0].z, rA[slot][0].w);
        v.z = pack_h2(rA[slot][1].x, rA[slot][1].y);
        v.w = pack_h2(rA[slot][1].z, rA[slot][1].w);
        *(uint4*)((char*)(sA16 + buf * STG_H) + st_off) = v;
    };
    auto cpB = [&](int buf, int kt) {
        cp16(sbB[buf] + st_off, Bb + kt * 16);
    };

    float acc[4][4][4];
    #pragma unroll
    for (int i = 0; i < 4; i++)
        #pragma unroll
        for (int j = 0; j < 4; j++)
            #pragma unroll
            for (int r = 0; r < 4; r++) acc[i][j][r] = 0.f;

    ldgA(0, 0); ldgA(1, 1);
    cpB(0, 0);  asm volatile("cp.async.commit_group;" ::: "memory");
    cpB(1, 1);  asm volatile("cp.async.commit_group;" ::: "memory");
    stsA(0, 0); ldgA(2, 0);

    int buf = 0;
    #pragma unroll 1
    for (int kt = 0; kt < NKT16; kt++) {
        if (kt < NKT16 - 1) {
            asm volatile("cp.async.wait_group 1;" ::: "memory");
        } else {
            asm volatile("cp.async.wait_group 0;" ::: "memory");
        }
        __syncthreads();

        if (kt + 2 < NKT16) {
            int nb = buf + 2; if (nb >= NST) nb -= NST;
            cpB(nb, kt + 2);
            asm volatile("cp.async.commit_group;" ::: "memory");
        }

        uint32_t a[4][4], b[4][2];
        #pragma unroll
        for (int mf = 0; mf < 4; mf++) {
            uint32_t addr = sbA[buf] + lds_a_off + (uint32_t)(mf * 16 * APITCH) * 2;
            asm volatile(
                "ldmatrix.sync.aligned.m8n8.x4.shared.b16 {%0,%1,%2,%3}, [%4];"
                : "=r"(a[mf][0]), "=r"(a[mf][1]), "=r"(a[mf][2]), "=r"(a[mf][3])
                : "r"(addr));
        }
        const __half* Bs = sB16 + buf * STG_H;
        #pragma unroll
        for (int nf = 0; nf < 4; nf++) {
            int rb = wn + nf * 8 + g;
            b[nf][0] = *(const uint32_t*)&Bs[rb * APITCH + tig * 2];
            b[nf][1] = *(const uint32_t*)&Bs[rb * APITCH + tig * 2 + 8];
        }
        #pragma unroll
        for (int mf = 0; mf < 4; mf++)
            #pragma unroll
            for (int nf = 0; nf < 4; nf++) {
                asm volatile(
                    "mma.sync.aligned.m16n8k16.row.col.f32.f16.f16.f32 "
                    "{%0,%1,%2,%3}, {%4,%5,%6,%7}, {%8,%9}, {%0,%1,%2,%3};"
                    : "+f"(acc[mf][nf][0]), "+f"(acc[mf][nf][1]),
                      "+f"(acc[mf][nf][2]), "+f"(acc[mf][nf][3])
                    : "r"(a[mf][0]), "r"(a[mf][1]), "r"(a[mf][2]), "r"(a[mf][3]),
                      "r"(b[nf][0]), "r"(b[nf][1]));
            }

        if (kt + 1 < NKT16) {
            int nb = buf + 1; if (nb >= NST) nb -= NST;
            stsA(nb, (kt + 1) & 1);
        }
        if (kt + 3 < NKT16) ldgA(kt + 3, (kt + 3) & 1);

        if (++buf == NST) buf = 0;
    }

    #pragma unroll
    for (int nf = 0; nf < 4; nf++) {
        const int col = n0 + wn + nf * 8 + tig * 2;
        const float2 bb = *(const float2*)(bias + col);
        #pragma unroll
        for (int mf = 0; mf < 4; mf++) {
            const int row = wm + mf * 16 + g;
            uint32_t h0 = pack_h2(acc[mf][nf][0] + bb.x, acc[mf][nf][1] + bb.y);
            uint32_t h1 = pack_h2(acc[mf][nf][2] + bb.x, acc[mf][nf][3] + bb.y);
            *(uint32_t*)(Crows + (size_t)row * HIDDEN + col) = h0;
            *(uint32_t*)(Crows + (size_t)(row + 8) * HIDDEN + col) = h1;
        }
    }
}

// ================= fp32-out fp16 MMA GEMM tile (GEMM2) =================
#define ROWPAD  20
#define BPITCH  24
#define A_STG   (128 * ROWPAD)
#define B_STG   (64 * BPITCH)
#define NSTAGE  3
#define NKT     (GK / 16)

__device__ void hgemm_tile(const float* __restrict__ A, const __half* __restrict__ Wt,
                           const float* __restrict__ bias, float* __restrict__ C,
                           int N, int m0, int n0, char* dynsm)
{
    float*  sA = (float*)dynsm;
    __half* sB = (__half*)(dynsm + NSTAGE * A_STG * 4);

    const int tid = threadIdx.x;
    const int wid = tid >> 5;
    const int lane = tid & 31;
    const int g = lane >> 2;
    const int tig = lane & 3;
    const int wm = (wid & 3) * 32;
    const int wn = (wid >> 2) * 32;

    float acc[2][4][4];
    #pragma unroll
    for (int i = 0; i < 2; i++)
        #pragma unroll
        for (int j = 0; j < 4; j++)
            #pragma unroll
            for (int r = 0; r < 4; r++) acc[i][j][r] = 0.f;

    uint32_t sbA[NSTAGE], sbB[NSTAGE];
    #pragma unroll
    for (int s = 0; s < NSTAGE; s++) {
        sbA[s] = smem_u32(sA + s * A_STG);
        sbB[s] = smem_u32(sB + s * B_STG);
    }

    auto load_stage = [&](int s, int kt) {
        #pragma unroll
        for (int i = 0; i < 2; i++) {
            int id = tid + i * 256;
            int row = id >> 2, c = id & 3;
            cp16(sbA[s] + (uint32_t)(row * ROWPAD + c * 4) * 4,
                 A + (size_t)(m0 + row) * GK + kt * 16 + c * 4);
        }
        if (tid < 128) {
            int row = tid >> 1, c = tid & 1;
            cp16(sbB[s] + (uint32_t)(row * BPITCH + c * 8) * 2,
                 Wt + (size_t)(n0 + row) * GK + kt * 16 + c * 8);
        }
    };

    load_stage(0, 0);
    asm volatile("cp.async.commit_group;" ::: "memory");
    load_stage(1, 1);
    asm volatile("cp.async.commit_group;" ::: "memory");

    #pragma unroll 1
    for (int kt = 0; kt < NKT; kt++) {
        if (kt < NKT - 1) {
            asm volatile("cp.async.wait_group 1;" ::: "memory");
        } else {
            asm volatile("cp.async.wait_group 0;" ::: "memory");
        }
        __syncthreads();

        if (kt + 2 < NKT) {
            load_stage((kt + 2) % NSTAGE, kt + 2);
            asm volatile("cp.async.commit_group;" ::: "memory");
        }

        const float*  As = sA + (kt % NSTAGE) * A_STG;
        const __half* Bs = sB + (kt % NSTAGE) * B_STG;

        uint32_t a[2][4], b[4][2];
        #pragma unroll
        for (int mf = 0; mf < 2; mf++) {
            int r = wm + mf * 16 + g;
            a[mf][0] = pack_h2(As[r * ROWPAD + tig * 2], As[r * ROWPAD + tig * 2 + 1]);
            a[mf][1] = pack_h2(As[(r + 8) * ROWPAD + tig * 2], As[(r + 8) * ROWPAD + tig * 2 + 1]);
            a[mf][2] = pack_h2(As[r * ROWPAD + tig * 2 + 8], As[r * ROWPAD + tig * 2 + 9]);
            a[mf][3] = pack_h2(As[(r + 8) * ROWPAD + tig * 2 + 8], As[(r + 8) * ROWPAD + tig * 2 + 9]);
        }
        #pragma unroll
        for (int nf = 0; nf < 4; nf++) {
            int rb = wn + nf * 8 + g;
            b[nf][0] = *(const uint32_t*)&Bs[rb * BPITCH + tig * 2];
            b[nf][1] = *(const uint32_t*)&Bs[rb * BPITCH + tig * 2 + 8];
        }
        #pragma unroll
        for (int mf = 0; mf < 2; mf++)
            #pragma unroll
            for (int nf = 0; nf < 4; nf++) {
                asm volatile(
                    "mma.sync.aligned.m16n8k16.row.col.f32.f16.f16.f32 "
                    "{%0,%1,%2,%3}, {%4,%5,%6,%7}, {%8,%9}, {%0,%1,%2,%3};"
                    : "+f"(acc[mf][nf][0]), "+f"(acc[mf][nf][1]),
                      "+f"(acc[mf][nf][2]), "+f"(acc[mf][nf][3])
                    : "r"(a[mf][0]), "r"(a[mf][1]), "r"(a[mf][2]), "r"(a[mf][3]),
                      "r"(b[nf][0]), "r"(b[nf][1]));
            }
    }

    #pragma unroll
    for (int nf = 0; nf < 4; nf++) {
        const int col = n0 + wn + nf * 8 + tig * 2;
        const float2 bb = *(const float2*)(bias + col);
        #pragma unroll
        for (int mf = 0; mf < 2; mf++) {
            const int row = m0 + wm + mf * 16 + g;
            float2 v0 = make_float2(acc[mf][nf][0] + bb.x, acc[mf][nf][1] + bb.y);
            float2 v1 = make_float2(acc[mf][nf][2] + bb.x, acc[mf][nf][3] + bb.y);
            *(float2*)(C + (size_t)row * N + col) = v0;
            *(float2*)(C + (size_t)(row + 8) * N + col) = v1;
        }
    }
}

// ================= GEMM3: 64x64 CTA tiles (high grid parallelism) =================
// 8 warps in 2(M)x4(N); warp tile 32x16. A fp32 -> cvt in-register; B fp16.
#define A3_STG  (64 * ROWPAD)      // floats per stage
#define B3_STG  (64 * BPITCH)      // halves per stage
#define G3_SMEM (NSTAGE * (A3_STG * 4 + B3_STG * 2))   // 24576 B

__global__ __launch_bounds__(256) void gemm3(const float* __restrict__ b_out,
                                             float* __restrict__ out)
{
    extern __shared__ char dynsm[];
    float*  sA = (float*)dynsm;
    __half* sB = (__half*)(dynsm + NSTAGE * A3_STG * 4);

    const int m0 = (blockIdx.x >> 2) * 64;
    const int n0 = (blockIdx.x & 3) * 64;
    const float* A = g_hidden;
    const __half* Wt = g_Wt3;

    const int tid = threadIdx.x;
    const int wid = tid >> 5;
    const int lane = tid & 31;
    const int g = lane >> 2;
    const int tig = lane & 3;
    const int wm = (wid & 1) * 32;
    const int wn = (wid >> 1) * 16;

    float acc[2][2][4];
    #pragma unroll
    for (int i = 0; i < 2; i++)
        #pragma unroll
        for (int j = 0; j < 2; j++)
            #pragma unroll
            for (int r = 0; r < 4; r++) acc[i][j][r] = 0.f;

    uint32_t sbA[NSTAGE], sbB[NSTAGE];
    #pragma unroll
    for (int s = 0; s < NSTAGE; s++) {
        sbA[s] = smem_u32(sA + s * A3_STG);
        sbB[s] = smem_u32(sB + s * B3_STG);
    }

    auto load_stage = [&](int s, int kt) {
        {   // A: 64 rows x 4 chunks = 256 -> one per thread
            int row = tid >> 2, c = tid & 3;
            cp16(sbA[s] + (uint32_t)(row * ROWPAD + c * 4) * 4,
                 A + (size_t)(m0 + row) * GK + kt * 16 + c * 4);
        }
        if (tid < 128) {   // B: 64 rows x 2 chunks
            int row = tid >> 1, c = tid & 1;
            cp16(sbB[s] + (uint32_t)(row * BPITCH + c * 8) * 2,
                 Wt + (size_t)(n0 + row) * GK + kt * 16 + c * 8);
        }
    };

    load_stage(0, 0);
    asm volatile("cp.async.commit_group;" ::: "memory");
    load_stage(1, 1);
    asm volatile("cp.async.commit_group;" ::: "memory");

    #pragma unroll 1
    for (int kt = 0; kt < NKT; kt++) {
        if (kt < NKT - 1) {
            asm volatile("cp.async.wait_group 1;" ::: "memory");
        } else {
            asm volatile("cp.async.wait_group 0;" ::: "memory");
        }
        __syncthreads();

        if (kt + 2 < NKT) {
            load_stage((kt + 2) % NSTAGE, kt + 2);
            asm volatile("cp.async.commit_group;" ::: "memory");
        }

        const float*  As = sA + (kt % NSTAGE) * A3_STG;
        const __half* Bs = sB + (kt % NSTAGE) * B3_STG;

        uint32_t a[2][4], b[2][2];
        #pragma unroll
        for (int mf = 0; mf < 2; mf++) {
            int r = wm + mf * 16 + g;
            a[mf][0] = pack_h2(As[r * ROWPAD + tig * 2], As[r * ROWPAD + tig * 2 + 1]);
            a[mf][1] = pack_h2(As[(r + 8) * ROWPAD + tig * 2], As[(r + 8) * ROWPAD + tig * 2 + 1]);
            a[mf][2] = pack_h2(As[r * ROWPAD + tig * 2 + 8], As[r * ROWPAD + tig * 2 + 9]);
            a[mf][3] = pack_h2(As[(r + 8) * ROWPAD + tig * 2 + 8], As[(r + 8) * ROWPAD + tig * 2 + 9]);
        }
        #pragma unroll
        for (int nf = 0; nf < 2; nf++) {
            int rb = wn + nf * 8 + g;
            b[nf][0] = *(const uint32_t*)&Bs[rb * BPITCH + tig * 2];
            b[nf][1] = *(const uint32_t*)&Bs[rb * BPITCH + tig * 2 + 8];
        }
        #pragma unroll
        for (int mf = 0; mf < 2; mf++)
            #pragma unroll
            for (int nf = 0; nf < 2; nf++) {
                asm volatile(
                    "mma.sync.aligned.m16n8k16.row.col.f32.f16.f16.f32 "
                    "{%0,%1,%2,%3}, {%4,%5,%6,%7}, {%8,%9}, {%0,%1,%2,%3};"
                    : "+f"(acc[mf][nf][0]), "+f"(acc[mf][nf][1]),
                      "+f"(acc[mf][nf][2]), "+f"(acc[mf][nf][3])
                    : "r"(a[mf][0]), "r"(a[mf][1]), "r"(a[mf][2]), "r"(a[mf][3]),
                      "r"(b[nf][0]), "r"(b[nf][1]));
            }
    }

    #pragma unroll
    for (int nf = 0; nf < 2; nf++) {
        const int col = n0 + wn + nf * 8 + tig * 2;
        const float2 bb = *(const float2*)(b_out + col);
        #pragma unroll
        for (int mf = 0; mf < 2; mf++) {
            const int row = m0 + wm + mf * 16 + g;
            float2 v0 = make_float2(acc[mf][nf][0] + bb.x, acc[mf][nf][1] + bb.y);
            float2 v1 = make_float2(acc[mf][nf][2] + bb.x, acc[mf][nf][3] + bb.y);
            *(float2*)(out + (size_t)row * HIDDEN + col) = v0;
            *(float2*)(out + (size_t)(row + 8) * HIDDEN + col) = v1;
        }
    }
}

// ================= launch A: GEMM2 segment + GEMM1 segment (independent) =================
__global__ __launch_bounds__(256, 2) void gemm_a(
    const float* __restrict__ img, const float* __restrict__ queries,
    const float* __restrict__ b_img, const float* __restrict__ b_q)
{
    extern __shared__ char dynsm[];
    int x = blockIdx.x;
    if (x < 384) {                       // GEMM2: [8192,256]@[256,384]
        hgemm_tile(queries, g_Wt2, b_q, g_qp, QPW, (x / 6) * 128, (x % 6) * 64, dynsm);
        return;
    }
    x -= 384;                            // GEMM1: 1360 slabs x 2 n-tiles
    const float* Ar = img + (size_t)(x >> 1) * 128 * GK;
    __half* Cr = g_img_p + (size_t)(x >> 1) * 128 * HIDDEN;
    gemm1_tile(Ar, g_Wt1, b_img, Cr, (x & 1) * 128, dynsm);
}

// ================= fused weight pack =================
__device__ void pack_body(const float* __restrict__ W, __half* __restrict__ Wt,
                          int N, int bx, int by)
{
    __shared__ float t[32][33];
    int x = threadIdx.x, y = threadIdx.y;
    #pragma unroll
    for (int i = 0; i < 32; i += 8)
        t[y + i][x] = W[(size_t)(by + y + i) * N + bx + x];
    __syncthreads();
    #pragma unroll
    for (int i = 0; i < 32; i += 8)
        Wt[(size_t)(bx + y + i) * GK + by + x] = __float2half_rn(t[x][y + i]);
}

__global__ void pack_all(const float* __restrict__ W1, const float* __restrict__ W2,
                         const float* __restrict__ W3)
{
    int x = blockIdx.x;
    if (x < 64)        pack_body(W1, g_Wt1, HIDDEN, (x & 7) * 32, (x >> 3) * 32);
    else if (x < 160)  { x -= 64;  pack_body(W2, g_Wt2, QPW, (x % 12) * 32, (x / 12) * 32); }
    else               { x -= 160; pack_body(W3, g_Wt3, EMBD, (x & 7) * 32, (x >> 3) * 32); }
}

// ================= fused prep + sampler: one warp per head =================
__global__ __launch_bounds__(256) void msda_fused(
    const __half* __restrict__ img_p, const float* __restrict__ qp,
    const float* __restrict__ refpts, float* __restrict__ out)
{
    __shared__ float s_w[8][64];
    __shared__ int   s_i[8][64];

    const int wslot = threadIdx.x >> 5;
    const int t = blockIdx.x * 8 + wslot;
    const int lane = threadIdx.x & 31;

    // ---- phase 1: per-sample prep on lanes 0-15 ----
    {
        const int s = lane & 15;
        const float* q = qp + (size_t)t * 48 + s * 3;
        float ox = q[0], oy = q[1], lg = q[2];

        float mx = lg;
        #pragma unroll
        for (int m = 1; m < 16; m <<= 1)
            mx = fmaxf(mx, __shfl_xor_sync(0xffffffff, mx, m));
        float e = expf(lg - mx);
        float sum = e;
        #pragma unroll
        for (int m = 1; m < 16; m <<= 1)
            sum += __shfl_xor_sync(0xffffffff, sum, m);
        float aw = e / sum;

        if (lane < 16) {
            const int bn = t / HNUM;
            const float rx = refpts[bn * 2 + 0];
            const float ry = refpts[bn * 2 + 1];

            const int l = s >> 2;
            const int sh = c_sh[l];
            const float fs = (float)sh;
            const int st = c_start[l];

            float x = (rx + ox / fs) * fs - 0.5f;
            float y = (ry + oy / fs) * fs - 0.5f;
            float x0f = floorf(x), y0f = floorf(y);
            int x0 = (int)x0f, y0 = (int)y0f;
            float wx = x - x0f, wy = y - y0f;

            float w00 = (1.f - wx) * (1.f - wy) * aw;
            float w10 = wx * (1.f - wy) * aw;
            float w01 = (1.f - wx) * wy * aw;
            float w11 = wx * wy * aw;

            bool vx0 = (x0 >= 0) & (x0 < sh);
            bool vx1 = (x0 + 1 >= 0) & (x0 + 1 < sh);
            bool vy0 = (y0 >= 0) & (y0 < sh);
            bool vy1 = (y0 + 1 >= 0) & (y0 + 1 < sh);

            int xc0 = min(max(x0, 0), sh - 1);
            int xc1 = min(max(x0 + 1, 0), sh - 1);
            int yc0 = min(max(y0, 0), sh - 1);
            int yc1 = min(max(y0 + 1, 0), sh - 1);

            s_w[wslot][s * 4 + 0] = (vx0 & vy0) ? w00 : 0.f;
            s_w[wslot][s * 4 + 1] = (vx1 & vy0) ? w10 : 0.f;
            s_w[wslot][s * 4 + 2] = (vx0 & vy1) ? w01 : 0.f;
            s_w[wslot][s * 4 + 3] = (vx1 & vy1) ? w11 : 0.f;

            s_i[wslot][s * 4 + 0] = (st + yc0 * sh + xc0) * HIDDEN;
            s_i[wslot][s * 4 + 1] = (st + yc0 * sh + xc1) * HIDDEN;
            s_i[wslot][s * 4 + 2] = (st + yc1 * sh + xc0) * HIDDEN;
            s_i[wslot][s * 4 + 3] = (st + yc1 * sh + xc1) * HIDDEN;
        }
    }
    __syncwarp();

    // ---- phase 2: gather ----
    const int cg = lane >> 2;
    const int seg = lane & 3;
    const int h = t & (HNUM - 1);
    const int b = t / (NQ * HNUM);
    const __half* base = img_p + (size_t)b * ITOT * HIDDEN + h * CHD + seg * 8;

    float acc[8];
    #pragma unroll
    for (int j = 0; j < 8; j++) acc[j] = 0.f;

    #pragma unroll
    for (int it = 0; it < 8; it++) {
        const int e = it * 8 + cg;
        const int idx = s_i[wslot][e];
        const float w = s_w[wslot][e];
        const uint4 v = *(const uint4*)(base + idx);
        const __half2* hv = (const __half2*)&v;
        #pragma unroll
        for (int j = 0; j < 4; j++) {
            float2 f = __half22float2(hv[j]);
            acc[2 * j]     += w * f.x;
            acc[2 * j + 1] += w * f.y;
        }
    }

    #pragma unroll
    for (int j = 0; j < 8; j++) {
        acc[j] += __shfl_xor_sync(0xffffffff, acc[j], 4);
        acc[j] += __shfl_xor_sync(0xffffffff, acc[j], 8);
        acc[j] += __shfl_xor_sync(0xffffffff, acc[j], 16);
    }

    if (cg == 0) {
        float* orow = out + (size_t)t * CHD + seg * 8;
        *(float4*)(orow)     = make_float4(acc[0], acc[1], acc[2], acc[3]);
        *(float4*)(orow + 4) = make_float4(acc[4], acc[5], acc[6], acc[7]);
    }
}

// ---------------- launch ----------------
#define DYN_SMEM 40960   // max(gemm1 36864, hgemm 39936)

extern "C" void kernel_launch(void* const* d_in, const int* in_sizes, int n_in,
                              void* d_out, int out_size)
{
    const float* img     = (const float*)d_in[0];
    const float* queries = (const float*)d_in[2];
    const float* refpts  = (const float*)d_in[3];
    const float* W_img   = (const float*)d_in[4];
    const float* b_img   = (const float*)d_in[5];
    const float* W_q     = (const float*)d_in[6];
    const float* b_q     = (const float*)d_in[7];
    const float* W_out   = (const float*)d_in[8];
    const float* b_out   = (const float*)d_in[9];
    float* out = (float*)d_out;

    float* qp;
    __half* img_p;
    float* hidden;
    cudaGetSymbolAddress((void**)&img_p,  g_img_p);
    cudaGetSymbolAddress((void**)&qp,     g_qp);
    cudaGetSymbolAddress((void**)&hidden, g_hidden);

    cudaFuncSetAttribute(gemm_a, cudaFuncAttributeMaxDynamicSharedMemorySize, DYN_SMEM);
    cudaFuncSetAttribute(gemm3,  cudaFuncAttributeMaxDynamicSharedMemorySize, G3_SMEM);

    // 0) pack all three weights (one launch)
    pack_all<<<224, dim3(32, 8)>>>(W_img, W_q, W_out);
    // 1) GEMM2 + GEMM1 merged (independent segments, one launch)
    gemm_a<<<384 + 2720, 256, DYN_SMEM>>>(img, queries, b_img, b_q);
    // 2) fused prep + sampler
    msda_fused<<<BNH / 8, 256>>>(img_p, qp, refpts, hidden);
    // 3) output projection: 128 m-tiles x 4 n-tiles of 64x64
    gemm3<<<512, 256, G3_SMEM>>>(b_out, out);
}

// round 14
// speedup vs baseline: 1.0344x; 1.0344x over previous
#include <cuda_runtime.h>
#include <cuda_fp16.h>
#include <cstdint>

// ---------------- problem constants ----------------
#define EMBD   256
#define HIDDEN 256
#define HNUM   8
#define CHD    32
#define BATCH  8
#define NQ     1024
#define ITOT   21760
#define QPW    384
#define GK     256
#define BNH    (BATCH * NQ * HNUM)   // 65536

// ---------------- scratch ----------------
__device__ __half  g_img_p[BATCH * ITOT * HIDDEN];
__device__ __half  g_Wt1[HIDDEN * GK];
__device__ __half  g_Wt2[QPW * GK];
__device__ __half  g_Wt3[EMBD * GK];
__device__ float   g_qp[BATCH * NQ * QPW];
__device__ __half  g_hidden16[BATCH * NQ * HIDDEN];   // fp16 sampled context

__constant__ int c_sh[4]    = {128, 64, 32, 16};
__constant__ int c_start[4] = {0, 16384, 20480, 21504};

// ---------------- helpers ----------------
__device__ __forceinline__ void cp16(uint32_t dst, const void* src) {
    asm volatile("cp.async.cg.shared.global [%0], [%1], 16;" :: "r"(dst), "l"(src));
}
__device__ __forceinline__ uint32_t smem_u32(const void* p) {
    uint32_t a;
    asm("{ .reg .u64 t; cvta.to.shared.u64 t, %1; cvt.u32.u64 %0, t; }" : "=r"(a) : "l"(p));
    return a;
}
__device__ __forceinline__ uint32_t pack_h2(float lo, float hi) {
    uint32_t r;
    asm("cvt.rn.f16x2.f32 %0, %1, %2;" : "=r"(r) : "f"(hi), "f"(lo));
    return r;
}

// ================= GEMM1 tile (fp16 MMA, f32 acc, ldmatrix), C fp16 =================
#define APITCH  24
#define STG_H   (128 * APITCH)
#define NST     3
#define NKT16   (GK / 16)

__device__ void gemm1_tile(const float* __restrict__ Arows, const __half* __restrict__ Wt,
                           const float* __restrict__ bias, __half* __restrict__ Crows,
                           int n0, char* dynsm)
{
    __half* sA16 = (__half*)dynsm;
    __half* sB16 = sA16 + NST * STG_H;

    const int tid = threadIdx.x;
    const int wid = tid >> 5;
    const int lane = tid & 31;
    const int g = lane >> 2;
    const int tig = lane & 3;
    const int wm = (wid & 1) * 64;
    const int wn = (wid >> 1) * 32;

    const uint32_t lds_a_off = (uint32_t)((wm + (lane & 15)) * APITCH + (lane >> 4) * 8) * 2;

    uint32_t sbA[NST], sbB[NST];
    #pragma unroll
    for (int s = 0; s < NST; s++) {
        sbA[s] = smem_u32(sA16 + s * STG_H);
        sbB[s] = smem_u32(sB16 + s * STG_H);
    }

    const int arow = tid >> 1, aseg = tid & 1;
    const float* Ab = Arows + (size_t)arow * GK + aseg * 8;
    const __half* Bb = Wt + (size_t)(n0 + arow) * GK + aseg * 8;
    const uint32_t st_off = (uint32_t)(arow * APITCH + aseg * 8) * 2;

    float4 rA[2][2];
    auto ldgA = [&](int kt, int slot) {
        const float* p = Ab + kt * 16;
        rA[slot][0] = *(const float4*)p;
        rA[slot][1] = *(const float4*)(p + 4);
    };
    auto stsA = [&](int buf, int slot) {
        uint4 v;
        v.x = pack_h2(rA[slot][0].x, rA[slot][0].y);
        v.y = pack_h2(rA[slot][0].z, rA[slot][0].w);
        v.z = pack_h2(rA[slot][1].x, rA[slot][1].y);
        v.w = pack_h2(rA[slot][1].z, rA[slot][1].w);
        *(uint4*)((char*)(sA16 + buf * STG_H) + st_off) = v;
    };
    auto cpB = [&](int buf, int kt) {
        cp16(sbB[buf] + st_off, Bb + kt * 16);
    };

    float acc[4][4][4];
    #pragma unroll
    for (int i = 0; i < 4; i++)
        #pragma unroll
        for (int j = 0; j < 4; j++)
            #pragma unroll
            for (int r = 0; r < 4; r++) acc[i][j][r] = 0.f;

    ldgA(0, 0); ldgA(1, 1);
    cpB(0, 0);  asm volatile("cp.async.commit_group;" ::: "memory");
    cpB(1, 1);  asm volatile("cp.async.commit_group;" ::: "memory");
    stsA(0, 0); ldgA(2, 0);

    int buf = 0;
    #pragma unroll 1
    for (int kt = 0; kt < NKT16; kt++) {
        if (kt < NKT16 - 1) {
            asm volatile("cp.async.wait_group 1;" ::: "memory");
        } else {
            asm volatile("cp.async.wait_group 0;" ::: "memory");
        }
        __syncthreads();

        if (kt + 2 < NKT16) {
            int nb = buf + 2; if (nb >= NST) nb -= NST;
            cpB(nb, kt + 2);
            asm volatile("cp.async.commit_group;" ::: "memory");
        }

        uint32_t a[4][4], b[4][2];
        #pragma unroll
        for (int mf = 0; mf < 4; mf++) {
            uint32_t addr = sbA[buf] + lds_a_off + (uint32_t)(mf * 16 * APITCH) * 2;
            asm volatile(
                "ldmatrix.sync.aligned.m8n8.x4.shared.b16 {%0,%1,%2,%3}, [%4];"
                : "=r"(a[mf][0]), "=r"(a[mf][1]), "=r"(a[mf][2]), "=r"(a[mf][3])
                : "r"(addr));
        }
        const __half* Bs = sB16 + buf * STG_H;
        #pragma unroll
        for (int nf = 0; nf < 4; nf++) {
            int rb = wn + nf * 8 + g;
            b[nf][0] = *(const uint32_t*)&Bs[rb * APITCH + tig * 2];
            b[nf][1] = *(const uint32_t*)&Bs[rb * APITCH + tig * 2 + 8];
        }
        #pragma unroll
        for (int mf = 0; mf < 4; mf++)
            #pragma unroll
            for (int nf = 0; nf < 4; nf++) {
                asm volatile(
                    "mma.sync.aligned.m16n8k16.row.col.f32.f16.f16.f32 "
                    "{%0,%1,%2,%3}, {%4,%5,%6,%7}, {%8,%9}, {%0,%1,%2,%3};"
                    : "+f"(acc[mf][nf][0]), "+f"(acc[mf][nf][1]),
                      "+f"(acc[mf][nf][2]), "+f"(acc[mf][nf][3])
                    : "r"(a[mf][0]), "r"(a[mf][1]), "r"(a[mf][2]), "r"(a[mf][3]),
                      "r"(b[nf][0]), "r"(b[nf][1]));
            }

        if (kt + 1 < NKT16) {
            int nb = buf + 1; if (nb >= NST) nb -= NST;
            stsA(nb, (kt + 1) & 1);
        }
        if (kt + 3 < NKT16) ldgA(kt + 3, (kt + 3) & 1);

        if (++buf == NST) buf = 0;
    }

    #pragma unroll
    for (int nf = 0; nf < 4; nf++) {
        const int col = n0 + wn + nf * 8 + tig * 2;
        const float2 bb = *(const float2*)(bias + col);
        #pragma unroll
        for (int mf = 0; mf < 4; mf++) {
            const int row = wm + mf * 16 + g;
            uint32_t h0 = pack_h2(acc[mf][nf][0] + bb.x, acc[mf][nf][1] + bb.y);
            uint32_t h1 = pack_h2(acc[mf][nf][2] + bb.x, acc[mf][nf][3] + bb.y);
            *(uint32_t*)(Crows + (size_t)row * HIDDEN + col) = h0;
            *(uint32_t*)(Crows + (size_t)(row + 8) * HIDDEN + col) = h1;
        }
    }
}

// ================= fp32-A fp16-B MMA GEMM tile (GEMM2) =================
#define ROWPAD  20
#define BPITCH  24
#define A_STG   (128 * ROWPAD)
#define B_STG   (64 * BPITCH)
#define NSTAGE  3
#define NKT     (GK / 16)

__device__ void hgemm_tile(const float* __restrict__ A, const __half* __restrict__ Wt,
                           const float* __restrict__ bias, float* __restrict__ C,
                           int N, int m0, int n0, char* dynsm)
{
    float*  sA = (float*)dynsm;
    __half* sB = (__half*)(dynsm + NSTAGE * A_STG * 4);

    const int tid = threadIdx.x;
    const int wid = tid >> 5;
    const int lane = tid & 31;
    const int g = lane >> 2;
    const int tig = lane & 3;
    const int wm = (wid & 3) * 32;
    const int wn = (wid >> 2) * 32;

    float acc[2][4][4];
    #pragma unroll
    for (int i = 0; i < 2; i++)
        #pragma unroll
        for (int j = 0; j < 4; j++)
            #pragma unroll
            for (int r = 0; r < 4; r++) acc[i][j][r] = 0.f;

    uint32_t sbA[NSTAGE], sbB[NSTAGE];
    #pragma unroll
    for (int s = 0; s < NSTAGE; s++) {
        sbA[s] = smem_u32(sA + s * A_STG);
        sbB[s] = smem_u32(sB + s * B_STG);
    }

    auto load_stage = [&](int s, int kt) {
        #pragma unroll
        for (int i = 0; i < 2; i++) {
            int id = tid + i * 256;
            int row = id >> 2, c = id & 3;
            cp16(sbA[s] + (uint32_t)(row * ROWPAD + c * 4) * 4,
                 A + (size_t)(m0 + row) * GK + kt * 16 + c * 4);
        }
        if (tid < 128) {
            int row = tid >> 1, c = tid & 1;
            cp16(sbB[s] + (uint32_t)(row * BPITCH + c * 8) * 2,
                 Wt + (size_t)(n0 + row) * GK + kt * 16 + c * 8);
        }
    };

    load_stage(0, 0);
    asm volatile("cp.async.commit_group;" ::: "memory");
    load_stage(1, 1);
    asm volatile("cp.async.commit_group;" ::: "memory");

    #pragma unroll 1
    for (int kt = 0; kt < NKT; kt++) {
        if (kt < NKT - 1) {
            asm volatile("cp.async.wait_group 1;" ::: "memory");
        } else {
            asm volatile("cp.async.wait_group 0;" ::: "memory");
        }
        __syncthreads();

        if (kt + 2 < NKT) {
            load_stage((kt + 2) % NSTAGE, kt + 2);
            asm volatile("cp.async.commit_group;" ::: "memory");
        }

        const float*  As = sA + (kt % NSTAGE) * A_STG;
        const __half* Bs = sB + (kt % NSTAGE) * B_STG;

        uint32_t a[2][4], b[4][2];
        #pragma unroll
        for (int mf = 0; mf < 2; mf++) {
            int r = wm + mf * 16 + g;
            a[mf][0] = pack_h2(As[r * ROWPAD + tig * 2], As[r * ROWPAD + tig * 2 + 1]);
            a[mf][1] = pack_h2(As[(r + 8) * ROWPAD + tig * 2], As[(r + 8) * ROWPAD + tig * 2 + 1]);
            a[mf][2] = pack_h2(As[r * ROWPAD + tig * 2 + 8], As[r * ROWPAD + tig * 2 + 9]);
            a[mf][3] = pack_h2(As[(r + 8) * ROWPAD + tig * 2 + 8], As[(r + 8) * ROWPAD + tig * 2 + 9]);
        }
        #pragma unroll
        for (int nf = 0; nf < 4; nf++) {
            int rb = wn + nf * 8 + g;
            b[nf][0] = *(const uint32_t*)&Bs[rb * BPITCH + tig * 2];
            b[nf][1] = *(const uint32_t*)&Bs[rb * BPITCH + tig * 2 + 8];
        }
        #pragma unroll
        for (int mf = 0; mf < 2; mf++)
            #pragma unroll
            for (int nf = 0; nf < 4; nf++) {
                asm volatile(
                    "mma.sync.aligned.m16n8k16.row.col.f32.f16.f16.f32 "
                    "{%0,%1,%2,%3}, {%4,%5,%6,%7}, {%8,%9}, {%0,%1,%2,%3};"
                    : "+f"(acc[mf][nf][0]), "+f"(acc[mf][nf][1]),
                      "+f"(acc[mf][nf][2]), "+f"(acc[mf][nf][3])
                    : "r"(a[mf][0]), "r"(a[mf][1]), "r"(a[mf][2]), "r"(a[mf][3]),
                      "r"(b[nf][0]), "r"(b[nf][1]));
            }
    }

    #pragma unroll
    for (int nf = 0; nf < 4; nf++) {
        const int col = n0 + wn + nf * 8 + tig * 2;
        const float2 bb = *(const float2*)(bias + col);
        #pragma unroll
        for (int mf = 0; mf < 2; mf++) {
            const int row = m0 + wm + mf * 16 + g;
            float2 v0 = make_float2(acc[mf][nf][0] + bb.x, acc[mf][nf][1] + bb.y);
            float2 v1 = make_float2(acc[mf][nf][2] + bb.x, acc[mf][nf][3] + bb.y);
            *(float2*)(C + (size_t)row * N + col) = v0;
            *(float2*)(C + (size_t)(row + 8) * N + col) = v1;
        }
    }
}

// ================= GEMM3 v3: fp16 A (g_hidden16), 128x64 tiles, ldmatrix A =================
// 8 warps 4(M)x2(N), warp tile 32x32.  A and B both fp16, APITCH-24 staging.
#define A3H_STG (128 * APITCH)       // halves per A stage (3072)
#define B3H_STG (64 * APITCH)        // halves per B stage (1536)
#define G3_SMEM (NST * (A3H_STG + B3H_STG) * 2)   // 27648 B

__global__ __launch_bounds__(256) void gemm3(const float* __restrict__ b_out,
                                             float* __restrict__ out)
{
    extern __shared__ char dynsm[];
    __half* sA = (__half*)dynsm;
    __half* sB = sA + NST * A3H_STG;

    const int m0 = (blockIdx.x >> 2) * 128;
    const int n0 = (blockIdx.x & 3) * 64;
    const __half* A = g_hidden16;
    const __half* Wt = g_Wt3;

    const int tid = threadIdx.x;
    const int wid = tid >> 5;
    const int lane = tid & 31;
    const int g = lane >> 2;
    const int tig = lane & 3;
    const int wm = (wid & 3) * 32;     // 4 warps over M
    const int wn = (wid >> 2) * 32;    // 2 warps over N

    const uint32_t lds_a_off = (uint32_t)((wm + (lane & 15)) * APITCH + (lane >> 4) * 8) * 2;

    uint32_t sbA[NST], sbB[NST];
    #pragma unroll
    for (int s = 0; s < NST; s++) {
        sbA[s] = smem_u32(sA + s * A3H_STG);
        sbB[s] = smem_u32(sB + s * B3H_STG);
    }

    auto load_stage = [&](int s, int kt) {
        {   // A: 128 rows x 2 chunks of 8 halves = 256 -> one per thread
            int row = tid >> 1, c = tid & 1;
            cp16(sbA[s] + (uint32_t)(row * APITCH + c * 8) * 2,
                 A + (size_t)(m0 + row) * GK + kt * 16 + c * 8);
        }
        if (tid < 128) {   // B: 64 rows x 2 chunks
            int row = tid >> 1, c = tid & 1;
            cp16(sbB[s] + (uint32_t)(row * APITCH + c * 8) * 2,
                 Wt + (size_t)(n0 + row) * GK + kt * 16 + c * 8);
        }
    };

    float acc[2][4][4];
    #pragma unroll
    for (int i = 0; i < 2; i++)
        #pragma unroll
        for (int j = 0; j < 4; j++)
            #pragma unroll
            for (int r = 0; r < 4; r++) acc[i][j][r] = 0.f;

    load_stage(0, 0);
    asm volatile("cp.async.commit_group;" ::: "memory");
    load_stage(1, 1);
    asm volatile("cp.async.commit_group;" ::: "memory");

    #pragma unroll 1
    for (int kt = 0; kt < NKT16; kt++) {
        if (kt < NKT16 - 1) {
            asm volatile("cp.async.wait_group 1;" ::: "memory");
        } else {
            asm volatile("cp.async.wait_group 0;" ::: "memory");
        }
        __syncthreads();

        if (kt + 2 < NKT16) {
            load_stage((kt + 2) % NST, kt + 2);
            asm volatile("cp.async.commit_group;" ::: "memory");
        }

        const int buf = kt % NST;
        uint32_t a[2][4], b[4][2];
        #pragma unroll
        for (int mf = 0; mf < 2; mf++) {
            uint32_t addr = sbA[buf] + lds_a_off + (uint32_t)(mf * 16 * APITCH) * 2;
            asm volatile(
                "ldmatrix.sync.aligned.m8n8.x4.shared.b16 {%0,%1,%2,%3}, [%4];"
                : "=r"(a[mf][0]), "=r"(a[mf][1]), "=r"(a[mf][2]), "=r"(a[mf][3])
                : "r"(addr));
        }
        const __half* Bs = sB + buf * B3H_STG;
        #pragma unroll
        for (int nf = 0; nf < 4; nf++) {
            int rb = wn + nf * 8 + g;
            b[nf][0] = *(const uint32_t*)&Bs[rb * APITCH + tig * 2];
            b[nf][1] = *(const uint32_t*)&Bs[rb * APITCH + tig * 2 + 8];
        }
        #pragma unroll
        for (int mf = 0; mf < 2; mf++)
            #pragma unroll
            for (int nf = 0; nf < 4; nf++) {
                asm volatile(
                    "mma.sync.aligned.m16n8k16.row.col.f32.f16.f16.f32 "
                    "{%0,%1,%2,%3}, {%4,%5,%6,%7}, {%8,%9}, {%0,%1,%2,%3};"
                    : "+f"(acc[mf][nf][0]), "+f"(acc[mf][nf][1]),
                      "+f"(acc[mf][nf][2]), "+f"(acc[mf][nf][3])
                    : "r"(a[mf][0]), "r"(a[mf][1]), "r"(a[mf][2]), "r"(a[mf][3]),
                      "r"(b[nf][0]), "r"(b[nf][1]));
            }
    }

    #pragma unroll
    for (int nf = 0; nf < 4; nf++) {
        const int col = n0 + wn + nf * 8 + tig * 2;
        const float2 bb = *(const float2*)(b_out + col);
        #pragma unroll
        for (int mf = 0; mf < 2; mf++) {
            const int row = m0 + wm + mf * 16 + g;
            float2 v0 = make_float2(acc[mf][nf][0] + bb.x, acc[mf][nf][1] + bb.y);
            float2 v1 = make_float2(acc[mf][nf][2] + bb.x, acc[mf][nf][3] + bb.y);
            *(float2*)(out + (size_t)row * HIDDEN + col) = v0;
            *(float2*)(out + (size_t)(row + 8) * HIDDEN + col) = v1;
        }
    }
}

// ================= launch A: GEMM2 segment + GEMM1 segment (independent) =================
__global__ __launch_bounds__(256, 2) void gemm_a(
    const float* __restrict__ img, const float* __restrict__ queries,
    const float* __restrict__ b_img, const float* __restrict__ b_q)
{
    extern __shared__ char dynsm[];
    int x = blockIdx.x;
    if (x < 384) {                       // GEMM2: [8192,256]@[256,384]
        hgemm_tile(queries, g_Wt2, b_q, g_qp, QPW, (x / 6) * 128, (x % 6) * 64, dynsm);
        return;
    }
    x -= 384;                            // GEMM1: 1360 slabs x 2 n-tiles
    const float* Ar = img + (size_t)(x >> 1) * 128 * GK;
    __half* Cr = g_img_p + (size_t)(x >> 1) * 128 * HIDDEN;
    gemm1_tile(Ar, g_Wt1, b_img, Cr, (x & 1) * 128, dynsm);
}

// ================= fused weight pack =================
__device__ void pack_body(const float* __restrict__ W, __half* __restrict__ Wt,
                          int N, int bx, int by)
{
    __shared__ float t[32][33];
    int x = threadIdx.x, y = threadIdx.y;
    #pragma unroll
    for (int i = 0; i < 32; i += 8)
        t[y + i][x] = W[(size_t)(by + y + i) * N + bx + x];
    __syncthreads();
    #pragma unroll
    for (int i = 0; i < 32; i += 8)
        Wt[(size_t)(bx + y + i) * GK + by + x] = __float2half_rn(t[x][y + i]);
}

__global__ void pack_all(const float* __restrict__ W1, const float* __restrict__ W2,
                         const float* __restrict__ W3)
{
    int x = blockIdx.x;
    if (x < 64)        pack_body(W1, g_Wt1, HIDDEN, (x & 7) * 32, (x >> 3) * 32);
    else if (x < 160)  { x -= 64;  pack_body(W2, g_Wt2, QPW, (x % 12) * 32, (x / 12) * 32); }
    else               { x -= 160; pack_body(W3, g_Wt3, EMBD, (x & 7) * 32, (x >> 3) * 32); }
}

// ================= fused prep + sampler: one warp per head, fp16 output =================
__global__ __launch_bounds__(256) void msda_fused(
    const __half* __restrict__ img_p, const float* __restrict__ qp,
    const float* __restrict__ refpts, __half* __restrict__ out)
{
    __shared__ float s_w[8][64];
    __shared__ int   s_i[8][64];

    const int wslot = threadIdx.x >> 5;
    const int t = blockIdx.x * 8 + wslot;
    const int lane = threadIdx.x & 31;

    // ---- phase 1: per-sample prep on lanes 0-15 ----
    {
        const int s = lane & 15;
        const float* q = qp + (size_t)t * 48 + s * 3;
        float ox = q[0], oy = q[1], lg = q[2];

        float mx = lg;
        #pragma unroll
        for (int m = 1; m < 16; m <<= 1)
            mx = fmaxf(mx, __shfl_xor_sync(0xffffffff, mx, m));
        float e = expf(lg - mx);
        float sum = e;
        #pragma unroll
        for (int m = 1; m < 16; m <<= 1)
            sum += __shfl_xor_sync(0xffffffff, sum, m);
        float aw = e / sum;

        if (lane < 16) {
            const int bn = t / HNUM;
            const float rx = refpts[bn * 2 + 0];
            const float ry = refpts[bn * 2 + 1];

            const int l = s >> 2;
            const int sh = c_sh[l];
            const float fs = (float)sh;
            const int st = c_start[l];

            float x = (rx + ox / fs) * fs - 0.5f;
            float y = (ry + oy / fs) * fs - 0.5f;
            float x0f = floorf(x), y0f = floorf(y);
            int x0 = (int)x0f, y0 = (int)y0f;
            float wx = x - x0f, wy = y - y0f;

            float w00 = (1.f - wx) * (1.f - wy) * aw;
            float w10 = wx * (1.f - wy) * aw;
            float w01 = (1.f - wx) * wy * aw;
            float w11 = wx * wy * aw;

            bool vx0 = (x0 >= 0) & (x0 < sh);
            bool vx1 = (x0 + 1 >= 0) & (x0 + 1 < sh);
            bool vy0 = (y0 >= 0) & (y0 < sh);
            bool vy1 = (y0 + 1 >= 0) & (y0 + 1 < sh);

            int xc0 = min(max(x0, 0), sh - 1);
            int xc1 = min(max(x0 + 1, 0), sh - 1);
            int yc0 = min(max(y0, 0), sh - 1);
            int yc1 = min(max(y0 + 1, 0), sh - 1);

            s_w[wslot][s * 4 + 0] = (vx0 & vy0) ? w00 : 0.f;
            s_w[wslot][s * 4 + 1] = (vx1 & vy0) ? w10 : 0.f;
            s_w[wslot][s * 4 + 2] = (vx0 & vy1) ? w01 : 0.f;
            s_w[wslot][s * 4 + 3] = (vx1 & vy1) ? w11 : 0.f;

            s_i[wslot][s * 4 + 0] = (st + yc0 * sh + xc0) * HIDDEN;
            s_i[wslot][s * 4 + 1] = (st + yc0 * sh + xc1) * HIDDEN;
            s_i[wslot][s * 4 + 2] = (st + yc1 * sh + xc0) * HIDDEN;
            s_i[wslot][s * 4 + 3] = (st + yc1 * sh + xc1) * HIDDEN;
        }
    }
    __syncwarp();

    // ---- phase 2: gather ----
    const int cg = lane >> 2;
    const int seg = lane & 3;
    const int h = t & (HNUM - 1);
    const int b = t / (NQ * HNUM);
    const __half* base = img_p + (size_t)b * ITOT * HIDDEN + h * CHD + seg * 8;

    float acc[8];
    #pragma unroll
    for (int j = 0; j < 8; j++) acc[j] = 0.f;

    #pragma unroll
    for (int it = 0; it < 8; it++) {
        const int e = it * 8 + cg;
        const int idx = s_i[wslot][e];
        const float w = s_w[wslot][e];
        const uint4 v = *(const uint4*)(base + idx);
        const __half2* hv = (const __half2*)&v;
        #pragma unroll
        for (int j = 0; j < 4; j++) {
            float2 f = __half22float2(hv[j]);
            acc[2 * j]     += w * f.x;
            acc[2 * j + 1] += w * f.y;
        }
    }

    #pragma unroll
    for (int j = 0; j < 8; j++) {
        acc[j] += __shfl_xor_sync(0xffffffff, acc[j], 4);
        acc[j] += __shfl_xor_sync(0xffffffff, acc[j], 8);
        acc[j] += __shfl_xor_sync(0xffffffff, acc[j], 16);
    }

    if (cg == 0) {
        __half* orow = out + (size_t)t * CHD + seg * 8;
        uint4 v;
        v.x = pack_h2(acc[0], acc[1]);
        v.y = pack_h2(acc[2], acc[3]);
        v.z = pack_h2(acc[4], acc[5]);
        v.w = pack_h2(acc[6], acc[7]);
        *(uint4*)orow = v;
    }
}

// ---------------- launch ----------------
#define DYN_SMEM 40960   // max(gemm1 36864, hgemm 39936)

extern "C" void kernel_launch(void* const* d_in, const int* in_sizes, int n_in,
                              void* d_out, int out_size)
{
    const float* img     = (const float*)d_in[0];
    const float* queries = (const float*)d_in[2];
    const float* refpts  = (const float*)d_in[3];
    const float* W_img   = (const float*)d_in[4];
    const float* b_img   = (const float*)d_in[5];
    const float* W_q     = (const float*)d_in[6];
    const float* b_q     = (const float*)d_in[7];
    const float* W_out   = (const float*)d_in[8];
    const float* b_out   = (const float*)d_in[9];
    float* out = (float*)d_out;

    float* qp;
    __half* img_p;
    __half* hidden16;
    cudaGetSymbolAddress((void**)&img_p,    g_img_p);
    cudaGetSymbolAddress((void**)&qp,       g_qp);
    cudaGetSymbolAddress((void**)&hidden16, g_hidden16);

    cudaFuncSetAttribute(gemm_a, cudaFuncAttributeMaxDynamicSharedMemorySize, DYN_SMEM);
    cudaFuncSetAttribute(gemm3,  cudaFuncAttributeMaxDynamicSharedMemorySize, G3_SMEM);

    // 0) pack all three weights (one launch)
    pack_all<<<224, dim3(32, 8)>>>(W_img, W_q, W_out);
    // 1) GEMM2 + GEMM1 merged (independent segments, one launch)
    gemm_a<<<384 + 2720, 256, DYN_SMEM>>>(img, queries, b_img, b_q);
    // 2) fused prep + sampler -> fp16 hidden
    msda_fused<<<BNH / 8, 256>>>(img_p, qp, refpts, hidden16);
    // 3) output projection: 64 m-tiles x 4 n-tiles of 128x64, fp16 A
    gemm3<<<256, 256, G3_SMEM>>>(b_out, out);
}

// round 15
// speedup vs baseline: 1.0411x; 1.0065x over previous
#include <cuda_runtime.h>
#include <cuda_fp16.h>
#include <cstdint>

// ---------------- problem constants ----------------
#define EMBD   256
#define HIDDEN 256
#define HNUM   8
#define CHD    32
#define BATCH  8
#define NQ     1024
#define ITOT   21760
#define QPW    384
#define GK     256
#define BNH    (BATCH * NQ * HNUM)   // 65536

// ---------------- scratch ----------------
__device__ __half  g_img_p[BATCH * ITOT * HIDDEN];
__device__ __half  g_Wt1[HIDDEN * GK];
__device__ __half  g_Wt2[QPW * GK];
__device__ __half  g_Wt3[EMBD * GK];
__device__ float   g_qp[BATCH * NQ * QPW];
__device__ __half  g_hidden16[BATCH * NQ * HIDDEN];   // fp16 sampled context

__constant__ int c_sh[4]    = {128, 64, 32, 16};
__constant__ int c_start[4] = {0, 16384, 20480, 21504};

// ---------------- helpers ----------------
__device__ __forceinline__ void cp16(uint32_t dst, const void* src) {
    asm volatile("cp.async.cg.shared.global [%0], [%1], 16;" :: "r"(dst), "l"(src));
}
__device__ __forceinline__ uint32_t smem_u32(const void* p) {
    uint32_t a;
    asm("{ .reg .u64 t; cvta.to.shared.u64 t, %1; cvt.u32.u64 %0, t; }" : "=r"(a) : "l"(p));
    return a;
}
__device__ __forceinline__ uint32_t pack_h2(float lo, float hi) {
    uint32_t r;
    asm("cvt.rn.f16x2.f32 %0, %1, %2;" : "=r"(r) : "f"(hi), "f"(lo));
    return r;
}

// ================= GEMM1 tile (fp16 MMA, f32 acc, ldmatrix), C fp16 =================
#define APITCH  24
#define STG_H   (128 * APITCH)
#define NST     3
#define NKT16   (GK / 16)

__device__ void gemm1_tile(const float* __restrict__ Arows, const __half* __restrict__ Wt,
                           const float* __restrict__ bias, __half* __restrict__ Crows,
                           int n0, char* dynsm)
{
    __half* sA16 = (__half*)dynsm;
    __half* sB16 = sA16 + NST * STG_H;

    const int tid = threadIdx.x;
    const int wid = tid >> 5;
    const int lane = tid & 31;
    const int g = lane >> 2;
    const int tig = lane & 3;
    const int wm = (wid & 1) * 64;
    const int wn = (wid >> 1) * 32;

    const uint32_t lds_a_off = (uint32_t)((wm + (lane & 15)) * APITCH + (lane >> 4) * 8) * 2;

    uint32_t sbA[NST], sbB[NST];
    #pragma unroll
    for (int s = 0; s < NST; s++) {
        sbA[s] = smem_u32(sA16 + s * STG_H);
        sbB[s] = smem_u32(sB16 + s * STG_H);
    }

    const int arow = tid >> 1, aseg = tid & 1;
    const float* Ab = Arows + (size_t)arow * GK + aseg * 8;
    const __half* Bb = Wt + (size_t)(n0 + arow) * GK + aseg * 8;
    const uint32_t st_off = (uint32_t)(arow * APITCH + aseg * 8) * 2;

    float4 rA[2][2];
    auto ldgA = [&](int kt, int slot) {
        const float* p = Ab + kt * 16;
        rA[slot][0] = *(const float4*)p;
        rA[slot][1] = *(const float4*)(p + 4);
    };
    auto stsA = [&](int buf, int slot) {
        uint4 v;
        v.x = pack_h2(rA[slot][0].x, rA[slot][0].y);
        v.y = pack_h2(rA[slot][0].z, rA[slot][0].w);
        v.z = pack_h2(rA[slot][1].x, rA[slot][1].y);
        v.w = pack_h2(rA[slot][1].z, rA[slot][1].w);
        *(uint4*)((char*)(sA16 + buf * STG_H) + st_off) = v;
    };
    auto cpB = [&](int buf, int kt) {
        cp16(sbB[buf] + st_off, Bb + kt * 16);
    };

    float acc[4][4][4];
    #pragma unroll
    for (int i = 0; i < 4; i++)
        #pragma unroll
        for (int j = 0; j < 4; j++)
            #pragma unroll
            for (int r = 0; r < 4; r++) acc[i][j][r] = 0.f;

    ldgA(0, 0); ldgA(1, 1);
    cpB(0, 0);  asm volatile("cp.async.commit_group;" ::: "memory");
    cpB(1, 1);  asm volatile("cp.async.commit_group;" ::: "memory");
    stsA(0, 0); ldgA(2, 0);

    int buf = 0;
    #pragma unroll 1
    for (int kt = 0; kt < NKT16; kt++) {
        if (kt < NKT16 - 1) {
            asm volatile("cp.async.wait_group 1;" ::: "memory");
        } else {
            asm volatile("cp.async.wait_group 0;" ::: "memory");
        }
        __syncthreads();

        if (kt + 2 < NKT16) {
            int nb = buf + 2; if (nb >= NST) nb -= NST;
            cpB(nb, kt + 2);
            asm volatile("cp.async.commit_group;" ::: "memory");
        }

        uint32_t a[4][4], b[4][2];
        #pragma unroll
        for (int mf = 0; mf < 4; mf++) {
            uint32_t addr = sbA[buf] + lds_a_off + (uint32_t)(mf * 16 * APITCH) * 2;
            asm volatile(
                "ldmatrix.sync.aligned.m8n8.x4.shared.b16 {%0,%1,%2,%3}, [%4];"
                : "=r"(a[mf][0]), "=r"(a[mf][1]), "=r"(a[mf][2]), "=r"(a[mf][3])
                : "r"(addr));
        }
        const __half* Bs = sB16 + buf * STG_H;
        #pragma unroll
        for (int nf = 0; nf < 4; nf++) {
            int rb = wn + nf * 8 + g;
            b[nf][0] = *(const uint32_t*)&Bs[rb * APITCH + tig * 2];
            b[nf][1] = *(const uint32_t*)&Bs[rb * APITCH + tig * 2 + 8];
        }
        #pragma unroll
        for (int mf = 0; mf < 4; mf++)
            #pragma unroll
            for (int nf = 0; nf < 4; nf++) {
                asm volatile(
                    "mma.sync.aligned.m16n8k16.row.col.f32.f16.f16.f32 "
                    "{%0,%1,%2,%3}, {%4,%5,%6,%7}, {%8,%9}, {%0,%1,%2,%3};"
                    : "+f"(acc[mf][nf][0]), "+f"(acc[mf][nf][1]),
                      "+f"(acc[mf][nf][2]), "+f"(acc[mf][nf][3])
                    : "r"(a[mf][0]), "r"(a[mf][1]), "r"(a[mf][2]), "r"(a[mf][3]),
                      "r"(b[nf][0]), "r"(b[nf][1]));
            }

        if (kt + 1 < NKT16) {
            int nb = buf + 1; if (nb >= NST) nb -= NST;
            stsA(nb, (kt + 1) & 1);
        }
        if (kt + 3 < NKT16) ldgA(kt + 3, (kt + 3) & 1);

        if (++buf == NST) buf = 0;
    }

    #pragma unroll
    for (int nf = 0; nf < 4; nf++) {
        const int col = n0 + wn + nf * 8 + tig * 2;
        const float2 bb = *(const float2*)(bias + col);
        #pragma unroll
        for (int mf = 0; mf < 4; mf++) {
            const int row = wm + mf * 16 + g;
            uint32_t h0 = pack_h2(acc[mf][nf][0] + bb.x, acc[mf][nf][1] + bb.y);
            uint32_t h1 = pack_h2(acc[mf][nf][2] + bb.x, acc[mf][nf][3] + bb.y);
            *(uint32_t*)(Crows + (size_t)row * HIDDEN + col) = h0;
            *(uint32_t*)(Crows + (size_t)(row + 8) * HIDDEN + col) = h1;
        }
    }
}

// ================= fp32-A fp16-B MMA GEMM tile (GEMM2) =================
#define ROWPAD  20
#define BPITCH  24
#define A_STG   (128 * ROWPAD)
#define B_STG   (64 * BPITCH)
#define NSTAGE  3
#define NKT     (GK / 16)

__device__ void hgemm_tile(const float* __restrict__ A, const __half* __restrict__ Wt,
                           const float* __restrict__ bias, float* __restrict__ C,
                           int N, int m0, int n0, char* dynsm)
{
    float*  sA = (float*)dynsm;
    __half* sB = (__half*)(dynsm + NSTAGE * A_STG * 4);

    const int tid = threadIdx.x;
    const int wid = tid >> 5;
    const int lane = tid & 31;
    const int g = lane >> 2;
    const int tig = lane & 3;
    const int wm = (wid & 3) * 32;
    const int wn = (wid >> 2) * 32;

    float acc[2][4][4];
    #pragma unroll
    for (int i = 0; i < 2; i++)
        #pragma unroll
        for (int j = 0; j < 4; j++)
            #pragma unroll
            for (int r = 0; r < 4; r++) acc[i][j][r] = 0.f;

    uint32_t sbA[NSTAGE], sbB[NSTAGE];
    #pragma unroll
    for (int s = 0; s < NSTAGE; s++) {
        sbA[s] = smem_u32(sA + s * A_STG);
        sbB[s] = smem_u32(sB + s * B_STG);
    }

    auto load_stage = [&](int s, int kt) {
        #pragma unroll
        for (int i = 0; i < 2; i++) {
            int id = tid + i * 256;
            int row = id >> 2, c = id & 3;
            cp16(sbA[s] + (uint32_t)(row * ROWPAD + c * 4) * 4,
                 A + (size_t)(m0 + row) * GK + kt * 16 + c * 4);
        }
        if (tid < 128) {
            int row = tid >> 1, c = tid & 1;
            cp16(sbB[s] + (uint32_t)(row * BPITCH + c * 8) * 2,
                 Wt + (size_t)(n0 + row) * GK + kt * 16 + c * 8);
        }
    };

    load_stage(0, 0);
    asm volatile("cp.async.commit_group;" ::: "memory");
    load_stage(1, 1);
    asm volatile("cp.async.commit_group;" ::: "memory");

    #pragma unroll 1
    for (int kt = 0; kt < NKT; kt++) {
        if (kt < NKT - 1) {
            asm volatile("cp.async.wait_group 1;" ::: "memory");
        } else {
            asm volatile("cp.async.wait_group 0;" ::: "memory");
        }
        __syncthreads();

        if (kt + 2 < NKT) {
            load_stage((kt + 2) % NSTAGE, kt + 2);
            asm volatile("cp.async.commit_group;" ::: "memory");
        }

        const float*  As = sA + (kt % NSTAGE) * A_STG;
        const __half* Bs = sB + (kt % NSTAGE) * B_STG;

        uint32_t a[2][4], b[4][2];
        #pragma unroll
        for (int mf = 0; mf < 2; mf++) {
            int r = wm + mf * 16 + g;
            a[mf][0] = pack_h2(As[r * ROWPAD + tig * 2], As[r * ROWPAD + tig * 2 + 1]);
            a[mf][1] = pack_h2(As[(r + 8) * ROWPAD + tig * 2], As[(r + 8) * ROWPAD + tig * 2 + 1]);
            a[mf][2] = pack_h2(As[r * ROWPAD + tig * 2 + 8], As[r * ROWPAD + tig * 2 + 9]);
            a[mf][3] = pack_h2(As[(r + 8) * ROWPAD + tig * 2 + 8], As[(r + 8) * ROWPAD + tig * 2 + 9]);
        }
        #pragma unroll
        for (int nf = 0; nf < 4; nf++) {
            int rb = wn + nf * 8 + g;
            b[nf][0] = *(const uint32_t*)&Bs[rb * BPITCH + tig * 2];
            b[nf][1] = *(const uint32_t*)&Bs[rb * BPITCH + tig * 2 + 8];
        }
        #pragma unroll
        for (int mf = 0; mf < 2; mf++)
            #pragma unroll
            for (int nf = 0; nf < 4; nf++) {
                asm volatile(
                    "mma.sync.aligned.m16n8k16.row.col.f32.f16.f16.f32 "
                    "{%0,%1,%2,%3}, {%4,%5,%6,%7}, {%8,%9}, {%0,%1,%2,%3};"
                    : "+f"(acc[mf][nf][0]), "+f"(acc[mf][nf][1]),
                      "+f"(acc[mf][nf][2]), "+f"(acc[mf][nf][3])
                    : "r"(a[mf][0]), "r"(a[mf][1]), "r"(a[mf][2]), "r"(a[mf][3]),
                      "r"(b[nf][0]), "r"(b[nf][1]));
            }
    }

    #pragma unroll
    for (int nf = 0; nf < 4; nf++) {
        const int col = n0 + wn + nf * 8 + tig * 2;
        const float2 bb = *(const float2*)(bias + col);
        #pragma unroll
        for (int mf = 0; mf < 2; mf++) {
            const int row = m0 + wm + mf * 16 + g;
            float2 v0 = make_float2(acc[mf][nf][0] + bb.x, acc[mf][nf][1] + bb.y);
            float2 v1 = make_float2(acc[mf][nf][2] + bb.x, acc[mf][nf][3] + bb.y);
            *(float2*)(C + (size_t)row * N + col) = v0;
            *(float2*)(C + (size_t)(row + 8) * N + col) = v1;
        }
    }
}

// ================= GEMM3 v4: fp16 A, 128x64 tiles, ldmatrix A, 5-stage pipeline =================
#define NST5    5
#define A3H_STG (128 * APITCH)       // halves per A stage (3072)
#define B3H_STG (64 * APITCH)        // halves per B stage (1536)
#define G3_SMEM (NST5 * (A3H_STG + B3H_STG) * 2)   // 46080 B

__global__ __launch_bounds__(256) void gemm3(const float* __restrict__ b_out,
                                             float* __restrict__ out)
{
    extern __shared__ char dynsm[];
    __half* sA = (__half*)dynsm;
    __half* sB = sA + NST5 * A3H_STG;

    const int m0 = (blockIdx.x >> 2) * 128;
    const int n0 = (blockIdx.x & 3) * 64;
    const __half* A = g_hidden16;
    const __half* Wt = g_Wt3;

    const int tid = threadIdx.x;
    const int wid = tid >> 5;
    const int lane = tid & 31;
    const int g = lane >> 2;
    const int tig = lane & 3;
    const int wm = (wid & 3) * 32;     // 4 warps over M
    const int wn = (wid >> 2) * 32;    // 2 warps over N

    const uint32_t lds_a_off = (uint32_t)((wm + (lane & 15)) * APITCH + (lane >> 4) * 8) * 2;

    uint32_t sbA[NST5], sbB[NST5];
    #pragma unroll
    for (int s = 0; s < NST5; s++) {
        sbA[s] = smem_u32(sA + s * A3H_STG);
        sbB[s] = smem_u32(sB + s * B3H_STG);
    }

    auto load_stage = [&](int s, int kt) {
        {   // A: 128 rows x 2 chunks of 8 halves = 256 -> one per thread
            int row = tid >> 1, c = tid & 1;
            cp16(sbA[s] + (uint32_t)(row * APITCH + c * 8) * 2,
                 A + (size_t)(m0 + row) * GK + kt * 16 + c * 8);
        }
        if (tid < 128) {   // B: 64 rows x 2 chunks
            int row = tid >> 1, c = tid & 1;
            cp16(sbB[s] + (uint32_t)(row * APITCH + c * 8) * 2,
                 Wt + (size_t)(n0 + row) * GK + kt * 16 + c * 8);
        }
    };

    float acc[2][4][4];
    #pragma unroll
    for (int i = 0; i < 2; i++)
        #pragma unroll
        for (int j = 0; j < 4; j++)
            #pragma unroll
            for (int r = 0; r < 4; r++) acc[i][j][r] = 0.f;

    // prologue: 4 stages in flight
    #pragma unroll
    for (int s = 0; s < 4; s++) {
        load_stage(s, s);
        asm volatile("cp.async.commit_group;" ::: "memory");
    }

    #pragma unroll 1
    for (int kt = 0; kt < NKT16; kt++) {
        if (kt < NKT16 - 3) {
            asm volatile("cp.async.wait_group 3;" ::: "memory");
        } else if (kt < NKT16 - 1) {
            asm volatile("cp.async.wait_group 1;" ::: "memory");
        } else {
            asm volatile("cp.async.wait_group 0;" ::: "memory");
        }
        __syncthreads();

        if (kt + 4 < NKT16) {
            load_stage((kt + 4) % NST5, kt + 4);
            asm volatile("cp.async.commit_group;" ::: "memory");
        }

        const int buf = kt % NST5;
        uint32_t a[2][4], b[4][2];
        #pragma unroll
        for (int mf = 0; mf < 2; mf++) {
            uint32_t addr = sbA[buf] + lds_a_off + (uint32_t)(mf * 16 * APITCH) * 2;
            asm volatile(
                "ldmatrix.sync.aligned.m8n8.x4.shared.b16 {%0,%1,%2,%3}, [%4];"
                : "=r"(a[mf][0]), "=r"(a[mf][1]), "=r"(a[mf][2]), "=r"(a[mf][3])
                : "r"(addr));
        }
        const __half* Bs = sB + buf * B3H_STG;
        #pragma unroll
        for (int nf = 0; nf < 4; nf++) {
            int rb = wn + nf * 8 + g;
            b[nf][0] = *(const uint32_t*)&Bs[rb * APITCH + tig * 2];
            b[nf][1] = *(const uint32_t*)&Bs[rb * APITCH + tig * 2 + 8];
        }
        #pragma unroll
        for (int mf = 0; mf < 2; mf++)
            #pragma unroll
            for (int nf = 0; nf < 4; nf++) {
                asm volatile(
                    "mma.sync.aligned.m16n8k16.row.col.f32.f16.f16.f32 "
                    "{%0,%1,%2,%3}, {%4,%5,%6,%7}, {%8,%9}, {%0,%1,%2,%3};"
                    : "+f"(acc[mf][nf][0]), "+f"(acc[mf][nf][1]),
                      "+f"(acc[mf][nf][2]), "+f"(acc[mf][nf][3])
                    : "r"(a[mf][0]), "r"(a[mf][1]), "r"(a[mf][2]), "r"(a[mf][3]),
                      "r"(b[nf][0]), "r"(b[nf][1]));
            }
    }

    #pragma unroll
    for (int nf = 0; nf < 4; nf++) {
        const int col = n0 + wn + nf * 8 + tig * 2;
        const float2 bb = *(const float2*)(b_out + col);
        #pragma unroll
        for (int mf = 0; mf < 2; mf++) {
            const int row = m0 + wm + mf * 16 + g;
            float2 v0 = make_float2(acc[mf][nf][0] + bb.x, acc[mf][nf][1] + bb.y);
            float2 v1 = make_float2(acc[mf][nf][2] + bb.x, acc[mf][nf][3] + bb.y);
            *(float2*)(out + (size_t)row * HIDDEN + col) = v0;
            *(float2*)(out + (size_t)(row + 8) * HIDDEN + col) = v1;
        }
    }
}

// ================= launch A: GEMM2 segment + GEMM1 segment (independent) =================
__global__ __launch_bounds__(256, 2) void gemm_a(
    const float* __restrict__ img, const float* __restrict__ queries,
    const float* __restrict__ b_img, const float* __restrict__ b_q)
{
    extern __shared__ char dynsm[];
    int x = blockIdx.x;
    if (x < 384) {                       // GEMM2: [8192,256]@[256,384]
        hgemm_tile(queries, g_Wt2, b_q, g_qp, QPW, (x / 6) * 128, (x % 6) * 64, dynsm);
        return;
    }
    x -= 384;                            // GEMM1: 1360 slabs x 2 n-tiles
    const float* Ar = img + (size_t)(x >> 1) * 128 * GK;
    __half* Cr = g_img_p + (size_t)(x >> 1) * 128 * HIDDEN;
    gemm1_tile(Ar, g_Wt1, b_img, Cr, (x & 1) * 128, dynsm);
}

// ================= fused weight pack =================
__device__ void pack_body(const float* __restrict__ W, __half* __restrict__ Wt,
                          int N, int bx, int by)
{
    __shared__ float t[32][33];
    int x = threadIdx.x, y = threadIdx.y;
    #pragma unroll
    for (int i = 0; i < 32; i += 8)
        t[y + i][x] = W[(size_t)(by + y + i) * N + bx + x];
    __syncthreads();
    #pragma unroll
    for (int i = 0; i < 32; i += 8)
        Wt[(size_t)(bx + y + i) * GK + by + x] = __float2half_rn(t[x][y + i]);
}

__global__ void pack_all(const float* __restrict__ W1, const float* __restrict__ W2,
                         const float* __restrict__ W3)
{
    int x = blockIdx.x;
    if (x < 64)        pack_body(W1, g_Wt1, HIDDEN, (x & 7) * 32, (x >> 3) * 32);
    else if (x < 160)  { x -= 64;  pack_body(W2, g_Wt2, QPW, (x % 12) * 32, (x / 12) * 32); }
    else               { x -= 160; pack_body(W3, g_Wt3, EMBD, (x & 7) * 32, (x >> 3) * 32); }
}

// ================= fused prep + sampler: one warp per head, fp16 output =================
__global__ __launch_bounds__(256) void msda_fused(
    const __half* __restrict__ img_p, const float* __restrict__ qp,
    const float* __restrict__ refpts, __half* __restrict__ out)
{
    __shared__ float s_w[8][64];
    __shared__ int   s_i[8][64];

    const int wslot = threadIdx.x >> 5;
    const int t = blockIdx.x * 8 + wslot;
    const int lane = threadIdx.x & 31;

    // ---- phase 1: per-sample prep on lanes 0-15 ----
    {
        const int s = lane & 15;
        const float* q = qp + (size_t)t * 48 + s * 3;
        float ox = q[0], oy = q[1], lg = q[2];

        float mx = lg;
        #pragma unroll
        for (int m = 1; m < 16; m <<= 1)
            mx = fmaxf(mx, __shfl_xor_sync(0xffffffff, mx, m));
        float e = expf(lg - mx);
        float sum = e;
        #pragma unroll
        for (int m = 1; m < 16; m <<= 1)
            sum += __shfl_xor_sync(0xffffffff, sum, m);
        float aw = e / sum;

        if (lane < 16) {
            const int bn = t / HNUM;
            const float rx = refpts[bn * 2 + 0];
            const float ry = refpts[bn * 2 + 1];

            const int l = s >> 2;
            const int sh = c_sh[l];
            const float fs = (float)sh;
            const int st = c_start[l];

            float x = (rx + ox / fs) * fs - 0.5f;
            float y = (ry + oy / fs) * fs - 0.5f;
            float x0f = floorf(x), y0f = floorf(y);
            int x0 = (int)x0f, y0 = (int)y0f;
            float wx = x - x0f, wy = y - y0f;

            float w00 = (1.f - wx) * (1.f - wy) * aw;
            float w10 = wx * (1.f - wy) * aw;
            float w01 = (1.f - wx) * wy * aw;
            float w11 = wx * wy * aw;

            bool vx0 = (x0 >= 0) & (x0 < sh);
            bool vx1 = (x0 + 1 >= 0) & (x0 + 1 < sh);
            bool vy0 = (y0 >= 0) & (y0 < sh);
            bool vy1 = (y0 + 1 >= 0) & (y0 + 1 < sh);

            int xc0 = min(max(x0, 0), sh - 1);
            int xc1 = min(max(x0 + 1, 0), sh - 1);
            int yc0 = min(max(y0, 0), sh - 1);
            int yc1 = min(max(y0 + 1, 0), sh - 1);

            s_w[wslot][s * 4 + 0] = (vx0 & vy0) ? w00 : 0.f;
            s_w[wslot][s * 4 + 1] = (vx1 & vy0) ? w10 : 0.f;
            s_w[wslot][s * 4 + 2] = (vx0 & vy1) ? w01 : 0.f;
            s_w[wslot][s * 4 + 3] = (vx1 & vy1) ? w11 : 0.f;

            s_i[wslot][s * 4 + 0] = (st + yc0 * sh + xc0) * HIDDEN;
            s_i[wslot][s * 4 + 1] = (st + yc0 * sh + xc1) * HIDDEN;
            s_i[wslot][s * 4 + 2] = (st + yc1 * sh + xc0) * HIDDEN;
            s_i[wslot][s * 4 + 3] = (st + yc1 * sh + xc1) * HIDDEN;
        }
    }
    __syncwarp();

    // ---- phase 2: gather ----
    const int cg = lane >> 2;
    const int seg = lane & 3;
    const int h = t & (HNUM - 1);
    const int b = t / (NQ * HNUM);
    const __half* base = img_p + (size_t)b * ITOT * HIDDEN + h * CHD + seg * 8;

    float acc[8];
    #pragma unroll
    for (int j = 0; j < 8; j++) acc[j] = 0.f;

    #pragma unroll
    for (int it = 0; it < 8; it++) {
        const int e = it * 8 + cg;
        const int idx = s_i[wslot][e];
        const float w = s_w[wslot][e];
        const uint4 v = *(const uint4*)(base + idx);
        const __half2* hv = (const __half2*)&v;
        #pragma unroll
        for (int j = 0; j < 4; j++) {
            float2 f = __half22float2(hv[j]);
            acc[2 * j]     += w * f.x;
            acc[2 * j + 1] += w * f.y;
        }
    }

    #pragma unroll
    for (int j = 0; j < 8; j++) {
        acc[j] += __shfl_xor_sync(0xffffffff, acc[j], 4);
        acc[j] += __shfl_xor_sync(0xffffffff, acc[j], 8);
        acc[j] += __shfl_xor_sync(0xffffffff, acc[j], 16);
    }

    if (cg == 0) {
        __half* orow = out + (size_t)t * CHD + seg * 8;
        uint4 v;
        v.x = pack_h2(acc[0], acc[1]);
        v.y = pack_h2(acc[2], acc[3]);
        v.z = pack_h2(acc[4], acc[5]);
        v.w = pack_h2(acc[6], acc[7]);
        *(uint4*)orow = v;
    }
}

// ---------------- launch ----------------
#define DYN_SMEM 40960   // max(gemm1 36864, hgemm 39936)

extern "C" void kernel_launch(void* const* d_in, const int* in_sizes, int n_in,
                              void* d_out, int out_size)
{
    const float* img     = (const float*)d_in[0];
    const float* queries = (const float*)d_in[2];
    const float* refpts  = (const float*)d_in[3];
    const float* W_img   = (const float*)d_in[4];
    const float* b_img   = (const float*)d_in[5];
    const float* W_q     = (const float*)d_in[6];
    const float* b_q     = (const float*)d_in[7];
    const float* W_out   = (const float*)d_in[8];
    const float* b_out   = (const float*)d_in[9];
    float* out = (float*)d_out;

    float* qp;
    __half* img_p;
    __half* hidden16;
    cudaGetSymbolAddress((void**)&img_p,    g_img_p);
    cudaGetSymbolAddress((void**)&qp,       g_qp);
    cudaGetSymbolAddress((void**)&hidden16, g_hidden16);

    cudaFuncSetAttribute(gemm_a, cudaFuncAttributeMaxDynamicSharedMemorySize, DYN_SMEM);
    cudaFuncSetAttribute(gemm3,  cudaFuncAttributeMaxDynamicSharedMemorySize, G3_SMEM);

    // 0) pack all three weights (one launch)
    pack_all<<<224, dim3(32, 8)>>>(W_img, W_q, W_out);
    // 1) GEMM2 + GEMM1 merged (independent segments, one launch)
    gemm_a<<<384 + 2720, 256, DYN_SMEM>>>(img, queries, b_img, b_q);
    // 2) fused prep + sampler -> fp16 hidden
    msda_fused<<<BNH / 8, 256>>>(img_p, qp, refpts, hidden16);
    // 3) output projection: 64 m-tiles x 4 n-tiles of 128x64, fp16 A, 5-stage
    gemm3<<<256, 256, G3_SMEM>>>(b_out, out);
}